// round 6
// baseline (speedup 1.0000x reference)
#include <cuda_runtime.h>
#include <cstdint>

#define N_NODES   100000
#define N_EDGES   1600000
#define N_ETYPES  3
#define IN_FEATS  128
#define HEADS     4
#define OUT_FEATS 16
#define HD        64
#define NEG_SLOPE 0.2f
#define SCAN_B    1024
#define NB        ((N_NODES + SCAN_B - 1) / SCAN_B)   // 98

// ---------------- device scratch (static globals; no allocation) -------------
__device__ float4 g_feat[N_NODES * 16];   // [N][64] as 16 x float4 (25.6 MB)
__device__ float4 g_el[N_NODES];          // [N][4]
__device__ float4 g_er[N_NODES];          // [N][4]
__device__ float4 g_ee[N_ETYPES];         // [3][4]
__device__ float4 g_z[N_NODES];           // invz per (node, head)
__device__ int    g_cnt[N_NODES];
__device__ int    g_incl[N_NODES];
__device__ int    g_bsum[NB];
__device__ int    g_boff[NB];
__device__ int    g_rowptr[N_NODES + 1];
__device__ int    g_cur[N_NODES];
__device__ int2   g_es[N_EDGES];          // sorted: {src, orig_id*4 | etype}

// ---------------- init: zero histogram ---------------------------------------
__global__ void k_init() {
    int i = blockIdx.x * 256 + threadIdx.x;
    if (i < N_NODES) g_cnt[i] = 0;
}

// ---------------- per-etype edge term ee[t][h] -------------------------------
__global__ void k_ee(const float* __restrict__ W_e, const float* __restrict__ attn_e,
                     const float* __restrict__ edge_emb) {
    int w = threadIdx.x >> 5, lane = threadIdx.x & 31;
    if (w >= N_ETYPES * HEADS) return;
    int t = w >> 2, h = w & 3;
    float acc = 0.0f;
#pragma unroll
    for (int ei = 0; ei < 2; ei++) {
        int e = lane + ei * 32;
        float dot = 0.0f;
#pragma unroll 8
        for (int k = 0; k < 64; k++)
            dot += edge_emb[t * 64 + k] * W_e[k * 256 + h * 64 + e];
        acc += dot * attn_e[h * 64 + e];
    }
#pragma unroll
    for (int o = 16; o; o >>= 1) acc += __shfl_xor_sync(0xffffffffu, acc, o);
    if (lane == 0) ((float*)g_ee)[t * 4 + h] = acc;
}

// ---------------- counting sort: histogram ------------------------------------
__global__ __launch_bounds__(256) void k_hist(const int* __restrict__ dst) {
    int i = blockIdx.x * 256 + threadIdx.x;
    if (i < N_EDGES) atomicAdd(&g_cnt[dst[i]], 1);
}

// ---------------- GEMM: feat = x @ W  (+ fused el/er epilogue) ---------------
__global__ __launch_bounds__(128) void k_gemm(const float* __restrict__ x,
                                              const float* __restrict__ W,
                                              const float* __restrict__ attn_l,
                                              const float* __restrict__ attn_r) {
    __shared__ float As[32][132];
    __shared__ float Bs[32][64];
    int tid = threadIdx.x;
    int tx = tid & 7, ty = tid >> 3;
    int rb = blockIdx.x * 128;
    float acc[8][8] = {};

    for (int k0 = 0; k0 < IN_FEATS; k0 += 32) {
#pragma unroll
        for (int i = 0; i < 8; i++) {
            int f   = tid + 128 * i;
            int row = f >> 3;
            int kq  = f & 7;
            float4 v = make_float4(0.f, 0.f, 0.f, 0.f);
            int gr = rb + row;
            if (gr < N_NODES) v = *(const float4*)&x[(long)gr * IN_FEATS + k0 + kq * 4];
            As[kq * 4 + 0][row] = v.x; As[kq * 4 + 1][row] = v.y;
            As[kq * 4 + 2][row] = v.z; As[kq * 4 + 3][row] = v.w;
        }
#pragma unroll
        for (int i = 0; i < 4; i++) {
            int f = tid + 128 * i;
            int k = f >> 4, c4 = f & 15;
            *(float4*)&Bs[k][c4 * 4] = *(const float4*)&W[(k0 + k) * HD + c4 * 4];
        }
        __syncthreads();
#pragma unroll
        for (int k = 0; k < 32; k++) {
            float4 a0 = *(float4*)&As[k][ty * 8];
            float4 a1 = *(float4*)&As[k][ty * 8 + 4];
            float4 b0 = *(float4*)&Bs[k][tx * 8];
            float4 b1 = *(float4*)&Bs[k][tx * 8 + 4];
            float av[8] = {a0.x, a0.y, a0.z, a0.w, a1.x, a1.y, a1.z, a1.w};
            float bv[8] = {b0.x, b0.y, b0.z, b0.w, b1.x, b1.y, b1.z, b1.w};
#pragma unroll
            for (int i = 0; i < 8; i++)
#pragma unroll
                for (int j = 0; j < 8; j++)
                    acc[i][j] += av[i] * bv[j];
        }
        __syncthreads();
    }

    int h = tx >> 1;
    int co = (tx & 1) * 8;
    float al[8], ar[8];
    *(float4*)&al[0] = *(const float4*)&attn_l[h * 16 + co];
    *(float4*)&al[4] = *(const float4*)&attn_l[h * 16 + co + 4];
    *(float4*)&ar[0] = *(const float4*)&attn_r[h * 16 + co];
    *(float4*)&ar[4] = *(const float4*)&attn_r[h * 16 + co + 4];
#pragma unroll
    for (int i = 0; i < 8; i++) {
        int r = rb + ty * 8 + i;
        float lp = 0.f, rp = 0.f;
#pragma unroll
        for (int j = 0; j < 8; j++) { lp += acc[i][j] * al[j]; rp += acc[i][j] * ar[j]; }
        lp += __shfl_xor_sync(0xffffffffu, lp, 1);
        rp += __shfl_xor_sync(0xffffffffu, rp, 1);
        if (r < N_NODES) {
            float* fr = (float*)&g_feat[(long)r * 16];
            *(float4*)&fr[tx * 8]     = make_float4(acc[i][0], acc[i][1], acc[i][2], acc[i][3]);
            *(float4*)&fr[tx * 8 + 4] = make_float4(acc[i][4], acc[i][5], acc[i][6], acc[i][7]);
            if ((tx & 1) == 0) {
                ((float*)g_el)[r * 4 + h] = lp;
                ((float*)g_er)[r * 4 + h] = rp;
            }
        }
    }
}

// ---------------- counting sort: scan + scatter -------------------------------
__global__ __launch_bounds__(SCAN_B) void k_scan1() {
    __shared__ int sh[SCAN_B];
    int b = blockIdx.x, t = threadIdx.x;
    int i = b * SCAN_B + t;
    sh[t] = (i < N_NODES) ? g_cnt[i] : 0;
#pragma unroll
    for (int o = 1; o < SCAN_B; o <<= 1) {
        __syncthreads();
        int add = (t >= o) ? sh[t - o] : 0;
        __syncthreads();
        sh[t] += add;
    }
    __syncthreads();
    if (i < N_NODES) g_incl[i] = sh[t];
    if (t == SCAN_B - 1) g_bsum[b] = sh[t];
}

__global__ void k_scan2() {
    __shared__ int sh[128];
    int t = threadIdx.x;
    int v = (t < NB) ? g_bsum[t] : 0;
    sh[t] = v;
#pragma unroll
    for (int o = 1; o < 128; o <<= 1) {
        __syncthreads();
        int add = (t >= o) ? sh[t - o] : 0;
        __syncthreads();
        sh[t] += add;
    }
    __syncthreads();
    if (t < NB) g_boff[t] = sh[t] - v;   // exclusive
}

__global__ void k_scan3() {
    int i = blockIdx.x * 256 + threadIdx.x;
    if (i < N_NODES) {
        int s = g_boff[i >> 10] + g_incl[i] - g_cnt[i];
        g_rowptr[i] = s;
        g_cur[i] = s;
    }
    if (i == 0) g_rowptr[N_NODES] = N_EDGES;
}

__global__ __launch_bounds__(256) void k_scatter(const int* __restrict__ src,
                                                 const int* __restrict__ dst,
                                                 const int* __restrict__ et) {
    int i = blockIdx.x * 256 + threadIdx.x;
    if (i >= N_EDGES) return;
    int p = atomicAdd(&g_cur[dst[i]], 1);
    g_es[p] = make_int2(src[i], (i << 2) | et[i]);
}

// ---------------- fused softmax + aggregate: one warp per dst node -----------
// 4 groups of 8 lanes; each group owns one in-flight edge. Lane gl covers
// float4-cols gl (heads 0/1) and gl+8 (heads 2/3). Unnormalized ev written
// scattered to out_a; invz stored to g_z; k_norm finishes a.
__global__ __launch_bounds__(256) void k_agg(float* __restrict__ rst,
                                             float* __restrict__ out_a) {
    int d = (blockIdx.x * 256 + threadIdx.x) >> 5;
    int lane = threadIdx.x & 31;
    if (d >= N_NODES) return;
    int start = g_rowptr[d], end = g_rowptr[d + 1];
    float4* rout4 = (float4*)(rst + (long)d * HD);
    int g = lane >> 3, gl = lane & 7;
    if (start == end) {
        if (g == 0) {
            rout4[gl]     = make_float4(0.f, 0.f, 0.f, 0.f);
            rout4[gl + 8] = make_float4(0.f, 0.f, 0.f, 0.f);
        }
        return;
    }

    const float* elf = (const float*)g_el;
    const float* erf = (const float*)g_er;
    const float* eef = (const float*)g_ee;

    int h0 = gl >> 2, h1 = h0 + 2;
    float er0 = erf[d * 4 + h0], er1 = erf[d * 4 + h1];
    float ee00 = eef[h0], ee01 = eef[4 + h0], ee02 = eef[8 + h0];
    float ee10 = eef[h1], ee11 = eef[4 + h1], ee12 = eef[8 + h1];

    float z0 = 0.f, z1 = 0.f;
    float4 acc0 = make_float4(0.f, 0.f, 0.f, 0.f);
    float4 acc1 = make_float4(0.f, 0.f, 0.f, 0.f);
    int e = start + g;
    int2 m = (e < end) ? g_es[e] : make_int2(0, 0);
    for (; e < end; e += 4) {
        int2 mn = m;
        if (e + 4 < end) mn = g_es[e + 4];           // prefetch next
        int t = m.y & 3;
        float e0 = (t == 0) ? ee00 : ((t == 1) ? ee01 : ee02);
        float e1 = (t == 0) ? ee10 : ((t == 1) ? ee11 : ee12);
        float sc0 = elf[m.x * 4 + h0] + er0 + e0;
        float sc1 = elf[m.x * 4 + h1] + er1 + e1;
        sc0 = sc0 > 0.f ? sc0 : NEG_SLOPE * sc0;
        sc1 = sc1 > 0.f ? sc1 : NEG_SLOPE * sc1;
        float ev0 = __expf(sc0), ev1 = __expf(sc1);
        z0 += ev0; z1 += ev1;
        float4 f0 = g_feat[(long)m.x * 16 + gl];
        float4 f1 = g_feat[(long)m.x * 16 + gl + 8];
        acc0.x += f0.x * ev0; acc0.y += f0.y * ev0;
        acc0.z += f0.z * ev0; acc0.w += f0.w * ev0;
        acc1.x += f1.x * ev1; acc1.y += f1.y * ev1;
        acc1.z += f1.z * ev1; acc1.w += f1.w * ev1;
        if ((gl & 3) == 0) {                          // lanes gl=0 (h 0,2), gl=4 (h 1,3)
            long orig = (long)(m.y >> 2);
            __stcs(&out_a[orig * 4 + h0], ev0);
            __stcs(&out_a[orig * 4 + h1], ev1);
        }
        m = mn;
    }
    // reduce over the 4 groups (lane bits 3,4), gl preserved
#pragma unroll
    for (int o = 8; o <= 16; o <<= 1) {
        z0     += __shfl_xor_sync(0xffffffffu, z0, o);
        z1     += __shfl_xor_sync(0xffffffffu, z1, o);
        acc0.x += __shfl_xor_sync(0xffffffffu, acc0.x, o);
        acc0.y += __shfl_xor_sync(0xffffffffu, acc0.y, o);
        acc0.z += __shfl_xor_sync(0xffffffffu, acc0.z, o);
        acc0.w += __shfl_xor_sync(0xffffffffu, acc0.w, o);
        acc1.x += __shfl_xor_sync(0xffffffffu, acc1.x, o);
        acc1.y += __shfl_xor_sync(0xffffffffu, acc1.y, o);
        acc1.z += __shfl_xor_sync(0xffffffffu, acc1.z, o);
        acc1.w += __shfl_xor_sync(0xffffffffu, acc1.w, o);
    }
    float iz0 = 1.0f / z0, iz1 = 1.0f / z1;
    if (g == 0) {
        rout4[gl]     = make_float4(acc0.x * iz0, acc0.y * iz0, acc0.z * iz0, acc0.w * iz0);
        rout4[gl + 8] = make_float4(acc1.x * iz1, acc1.y * iz1, acc1.z * iz1, acc1.w * iz1);
        if ((gl & 3) == 0) {
            ((float*)g_z)[d * 4 + h0] = iz0;
            ((float*)g_z)[d * 4 + h1] = iz1;
        }
    }
}

// ---------------- normalize a: edge-parallel, coalesced -----------------------
__global__ __launch_bounds__(256) void k_norm(const int* __restrict__ dst,
                                              float4* __restrict__ out_a4) {
    int i = blockIdx.x * 256 + threadIdx.x;
    if (i >= N_EDGES) return;
    float4 a = out_a4[i];
    float4 iz = g_z[dst[i]];
    a.x *= iz.x; a.y *= iz.y; a.z *= iz.z; a.w *= iz.w;
    out_a4[i] = a;
}

// ---------------- launch ------------------------------------------------------
extern "C" void kernel_launch(void* const* d_in, const int* in_sizes, int n_in,
                              void* d_out, int out_size) {
    const float* x        = (const float*)d_in[0];
    const float* W        = (const float*)d_in[1];
    const float* W_e      = (const float*)d_in[2];
    const float* attn_l   = (const float*)d_in[3];
    const float* attn_r   = (const float*)d_in[4];
    const float* attn_e   = (const float*)d_in[5];
    const float* edge_emb = (const float*)d_in[6];
    const int*   src      = (const int*)d_in[7];
    const int*   dst      = (const int*)d_in[8];
    const int*   et       = (const int*)d_in[9];

    float* rst   = (float*)d_out;
    float* out_a = rst + (long)N_NODES * HD;

    int nb = (N_NODES + 255) / 256;
    int eb = (N_EDGES + 255) / 256;

    k_init<<<nb, 256>>>();
    k_ee<<<1, 384>>>(W_e, attn_e, edge_emb);
    k_hist<<<eb, 256>>>(dst);
    k_gemm<<<(N_NODES + 127) / 128, 128>>>(x, W, attn_l, attn_r);   // 4th: profiled
    k_scan1<<<NB, SCAN_B>>>();
    k_scan2<<<1, 128>>>();
    k_scan3<<<nb, 256>>>();
    k_scatter<<<eb, 256>>>(src, dst, et);
    k_agg<<<(N_NODES * 32 + 255) / 256, 256>>>(rst, out_a);
    k_norm<<<eb, 256>>>(dst, (float4*)out_a);
}

// round 7
// speedup vs baseline: 1.2242x; 1.2242x over previous
#include <cuda_runtime.h>
#include <cstdint>

#define N_NODES   100000
#define N_EDGES   1600000
#define N_ETYPES  3
#define IN_FEATS  128
#define HEADS     4
#define OUT_FEATS 16
#define HD        64
#define NEG_SLOPE 0.2f
#define SCAN_B    1024
#define NB        ((N_NODES + SCAN_B - 1) / SCAN_B)   // 98

// ---------------- device scratch (static globals; no allocation) -------------
__device__ float4 g_feat[N_NODES * 16];   // [N][64] as 16 x float4 (25.6 MB)
__device__ float4 g_el[N_NODES];          // [N][4]
__device__ float4 g_er[N_NODES];          // [N][4]
__device__ float4 g_ee[N_ETYPES];         // [3][4]
__device__ int    g_cnt[N_NODES];
__device__ int    g_incl[N_NODES];
__device__ int    g_bsum[NB];
__device__ int    g_boff[NB];
__device__ int    g_rowptr[N_NODES + 1];
__device__ int    g_cur[N_NODES];
__device__ int2   g_es[N_EDGES];          // sorted: {src, orig_id*4 | etype}

__device__ __forceinline__ uint32_t to_tf32(float f) {
    uint32_t r;
    asm("cvt.rna.tf32.f32 %0, %1;" : "=r"(r) : "f"(f));
    return r;
}

__device__ __forceinline__ void mma_tf32(float* c, const uint32_t* a, const uint32_t* b) {
    asm("mma.sync.aligned.m16n8k8.row.col.f32.tf32.tf32.f32 "
        "{%0,%1,%2,%3}, {%4,%5,%6,%7}, {%8,%9}, {%0,%1,%2,%3};"
        : "+f"(c[0]), "+f"(c[1]), "+f"(c[2]), "+f"(c[3])
        : "r"(a[0]), "r"(a[1]), "r"(a[2]), "r"(a[3]), "r"(b[0]), "r"(b[1]));
}

// ---------------- init: zero histogram ---------------------------------------
__global__ void k_init() {
    int i = blockIdx.x * 256 + threadIdx.x;
    if (i < N_NODES) g_cnt[i] = 0;
}

// ---------------- per-etype edge term ee[t][h] -------------------------------
__global__ void k_ee(const float* __restrict__ W_e, const float* __restrict__ attn_e,
                     const float* __restrict__ edge_emb) {
    int w = threadIdx.x >> 5, lane = threadIdx.x & 31;
    if (w >= N_ETYPES * HEADS) return;
    int t = w >> 2, h = w & 3;
    float acc = 0.0f;
#pragma unroll
    for (int ei = 0; ei < 2; ei++) {
        int e = lane + ei * 32;
        float dot = 0.0f;
#pragma unroll 8
        for (int k = 0; k < 64; k++)
            dot += edge_emb[t * 64 + k] * W_e[k * 256 + h * 64 + e];
        acc += dot * attn_e[h * 64 + e];
    }
#pragma unroll
    for (int o = 16; o; o >>= 1) acc += __shfl_xor_sync(0xffffffffu, acc, o);
    if (lane == 0) ((float*)g_ee)[t * 4 + h] = acc;
}

// ---------------- counting sort: histogram ------------------------------------
__global__ __launch_bounds__(256) void k_hist(const int* __restrict__ dst) {
    int i = blockIdx.x * 256 + threadIdx.x;
    if (i < N_EDGES) atomicAdd(&g_cnt[dst[i]], 1);
}

// ---------------- GEMM: feat = x @ W via tf32 HMMA (+ fused el/er epilogue) --
// 128x64 per block, 8 warps (4x2), warp tile 32x32 = 2(m16) x 4(n8) mma frags.
__global__ __launch_bounds__(256) void k_gemm(const float* __restrict__ x,
                                              const float* __restrict__ W,
                                              const float* __restrict__ attn_l,
                                              const float* __restrict__ attn_r) {
    // As: [row][40] fp32-as-tf32; float4-col XOR swizzle (^((row>>2)&1)).
    // Bs: [k][72]; both conflict-free for frag loads + staging stores.
    __shared__ uint32_t As[128][40];
    __shared__ uint32_t Bs[32][72];
    int tid  = threadIdx.x;
    int lane = tid & 31, wid = tid >> 5;
    int warp_m = wid & 3, warp_n = wid >> 2;
    int g = lane >> 2, t = lane & 3;
    int rbase = warp_m * 32, cbase = warp_n * 32;
    int rb = blockIdx.x * 128;

    float acc[2][4][4] = {};

    for (int k0 = 0; k0 < IN_FEATS; k0 += 32) {
        // stage A: 128 rows x 32 k
#pragma unroll
        for (int i = 0; i < 4; i++) {
            int s = tid + 256 * i;          // float4 slot 0..1023
            int row = s >> 3, kq = s & 7;
            float4 v = make_float4(0.f, 0.f, 0.f, 0.f);
            int gr = rb + row;
            if (gr < N_NODES) v = *(const float4*)&x[(long)gr * IN_FEATS + k0 + kq * 4];
            int kp = kq ^ ((row >> 2) & 1);
            *(uint4*)&As[row][kp * 4] =
                make_uint4(to_tf32(v.x), to_tf32(v.y), to_tf32(v.z), to_tf32(v.w));
        }
        // stage B: 32 k x 64 n
#pragma unroll
        for (int i = 0; i < 2; i++) {
            int s = tid + 256 * i;          // float4 slot 0..511
            int k = s >> 4, c4 = s & 15;
            float4 v = *(const float4*)&W[(long)(k0 + k) * HD + c4 * 4];
            *(uint4*)&Bs[k][c4 * 4] =
                make_uint4(to_tf32(v.x), to_tf32(v.y), to_tf32(v.z), to_tf32(v.w));
        }
        __syncthreads();

#pragma unroll
        for (int ks = 0; ks < 4; ks++) {
            int kk = ks * 8;
            uint32_t a[2][4];
#pragma unroll
            for (int mt = 0; mt < 2; mt++) {
                int r0 = rbase + mt * 16 + g;
                int c0 = kk + t, c1 = kk + t + 4;
                int p0 = ((c0 >> 2) ^ ((r0 >> 2) & 1)) * 4 + (c0 & 3);
                int p0b = ((c0 >> 2) ^ (((r0 + 8) >> 2) & 1)) * 4 + (c0 & 3);
                int p1 = ((c1 >> 2) ^ ((r0 >> 2) & 1)) * 4 + (c1 & 3);
                int p1b = ((c1 >> 2) ^ (((r0 + 8) >> 2) & 1)) * 4 + (c1 & 3);
                a[mt][0] = As[r0][p0];
                a[mt][1] = As[r0 + 8][p0b];
                a[mt][2] = As[r0][p1];
                a[mt][3] = As[r0 + 8][p1b];
            }
            uint32_t b[4][2];
#pragma unroll
            for (int nt = 0; nt < 4; nt++) {
                int n = cbase + nt * 8 + g;
                b[nt][0] = Bs[kk + t][n];
                b[nt][1] = Bs[kk + t + 4][n];
            }
#pragma unroll
            for (int mt = 0; mt < 2; mt++)
#pragma unroll
                for (int nt = 0; nt < 4; nt++)
                    mma_tf32(acc[mt][nt], a[mt], b[nt]);
        }
        __syncthreads();
    }

    // ---- epilogue: feat store + el/er dots
    int hA = warp_n * 2, hB = hA + 1;
    float2 alA[2], arA[2], alB[2], arB[2];
#pragma unroll
    for (int q = 0; q < 2; q++) {
        alA[q] = *(const float2*)&attn_l[hA * 16 + q * 8 + t * 2];
        arA[q] = *(const float2*)&attn_r[hA * 16 + q * 8 + t * 2];
        alB[q] = *(const float2*)&attn_l[hB * 16 + q * 8 + t * 2];
        arB[q] = *(const float2*)&attn_r[hB * 16 + q * 8 + t * 2];
    }
    float* gfeat = (float*)g_feat;
#pragma unroll
    for (int mt = 0; mt < 2; mt++)
#pragma unroll
    for (int rr = 0; rr < 2; rr++) {
        int r = rb + rbase + mt * 16 + g + rr * 8;
        float v[4][2];
#pragma unroll
        for (int nt = 0; nt < 4; nt++) {
            v[nt][0] = acc[mt][nt][rr * 2];
            v[nt][1] = acc[mt][nt][rr * 2 + 1];
        }
        if (r < N_NODES) {
#pragma unroll
            for (int nt = 0; nt < 4; nt++)
                *(float2*)&gfeat[(long)r * HD + cbase + nt * 8 + t * 2] =
                    make_float2(v[nt][0], v[nt][1]);
        }
        float elA = v[0][0] * alA[0].x + v[0][1] * alA[0].y + v[1][0] * alA[1].x + v[1][1] * alA[1].y;
        float erA = v[0][0] * arA[0].x + v[0][1] * arA[0].y + v[1][0] * arA[1].x + v[1][1] * arA[1].y;
        float elB = v[2][0] * alB[0].x + v[2][1] * alB[0].y + v[3][0] * alB[1].x + v[3][1] * alB[1].y;
        float erB = v[2][0] * arB[0].x + v[2][1] * arB[0].y + v[3][0] * arB[1].x + v[3][1] * arB[1].y;
#pragma unroll
        for (int o = 1; o <= 2; o <<= 1) {
            elA += __shfl_xor_sync(0xffffffffu, elA, o);
            erA += __shfl_xor_sync(0xffffffffu, erA, o);
            elB += __shfl_xor_sync(0xffffffffu, elB, o);
            erB += __shfl_xor_sync(0xffffffffu, erB, o);
        }
        if (t == 0 && r < N_NODES) {
            ((float*)g_el)[r * 4 + hA] = elA;
            ((float*)g_el)[r * 4 + hB] = elB;
            ((float*)g_er)[r * 4 + hA] = erA;
            ((float*)g_er)[r * 4 + hB] = erB;
        }
    }
}

// ---------------- counting sort: scan + scatter -------------------------------
__global__ __launch_bounds__(SCAN_B) void k_scan1() {
    __shared__ int sh[SCAN_B];
    int b = blockIdx.x, t = threadIdx.x;
    int i = b * SCAN_B + t;
    sh[t] = (i < N_NODES) ? g_cnt[i] : 0;
#pragma unroll
    for (int o = 1; o < SCAN_B; o <<= 1) {
        __syncthreads();
        int add = (t >= o) ? sh[t - o] : 0;
        __syncthreads();
        sh[t] += add;
    }
    __syncthreads();
    if (i < N_NODES) g_incl[i] = sh[t];
    if (t == SCAN_B - 1) g_bsum[b] = sh[t];
}

__global__ void k_scan2() {
    __shared__ int sh[128];
    int t = threadIdx.x;
    int v = (t < NB) ? g_bsum[t] : 0;
    sh[t] = v;
#pragma unroll
    for (int o = 1; o < 128; o <<= 1) {
        __syncthreads();
        int add = (t >= o) ? sh[t - o] : 0;
        __syncthreads();
        sh[t] += add;
    }
    __syncthreads();
    if (t < NB) g_boff[t] = sh[t] - v;   // exclusive
}

__global__ void k_scan3() {
    int i = blockIdx.x * 256 + threadIdx.x;
    if (i < N_NODES) {
        int s = g_boff[i >> 10] + g_incl[i] - g_cnt[i];
        g_rowptr[i] = s;
        g_cur[i] = s;
    }
    if (i == 0) g_rowptr[N_NODES] = N_EDGES;
}

__global__ __launch_bounds__(256) void k_scatter(const int* __restrict__ src,
                                                 const int* __restrict__ dst,
                                                 const int* __restrict__ et) {
    int i = blockIdx.x * 256 + threadIdx.x;
    if (i >= N_EDGES) return;
    int p = atomicAdd(&g_cur[dst[i]], 1);
    g_es[p] = make_int2(src[i], (i << 2) | et[i]);
}

// ---------------- fused softmax + aggregate: one warp per dst node -----------
__global__ __launch_bounds__(256) void k_agg(float* __restrict__ rst,
                                             float* __restrict__ out_a) {
    int d = (blockIdx.x * 256 + threadIdx.x) >> 5;
    int lane = threadIdx.x & 31;
    if (d >= N_NODES) return;
    int start = g_rowptr[d], end = g_rowptr[d + 1];
    float4* rout4 = (float4*)(rst + (long)d * HD);
    int sl = lane & 15, half = lane >> 4;
    if (start == end) {
        if (half == 0) rout4[sl] = make_float4(0.f, 0.f, 0.f, 0.f);
        return;
    }

    const float* elf = (const float*)g_el;
    const float* erf = (const float*)g_er;
    const float* eef = (const float*)g_ee;

    int h = sl >> 2;
    float erh = erf[d * 4 + h];
    float ee0 = eef[h], ee1 = eef[4 + h], ee2 = eef[8 + h];

    float z = 0.f;
    float4 acc = make_float4(0.f, 0.f, 0.f, 0.f);
    int e = start + half;
    int2 m = (e < end) ? g_es[e] : make_int2(0, 0);
    for (; e < end; e += 2) {
        int2 mn = m;
        if (e + 2 < end) mn = g_es[e + 2];
        int t = m.y & 3;
        float eet = (t == 0) ? ee0 : ((t == 1) ? ee1 : ee2);
        float sc = elf[m.x * 4 + h] + erh + eet;
        sc = sc > 0.f ? sc : NEG_SLOPE * sc;
        float ev = __expf(sc);
        float4 f = g_feat[(long)m.x * 16 + sl];
        z += ev;
        acc.x += f.x * ev; acc.y += f.y * ev;
        acc.z += f.z * ev; acc.w += f.w * ev;
        m = mn;
    }
    z     += __shfl_xor_sync(0xffffffffu, z, 16);
    acc.x += __shfl_xor_sync(0xffffffffu, acc.x, 16);
    acc.y += __shfl_xor_sync(0xffffffffu, acc.y, 16);
    acc.z += __shfl_xor_sync(0xffffffffu, acc.z, 16);
    acc.w += __shfl_xor_sync(0xffffffffu, acc.w, 16);
    float invz = 1.0f / z;
    if (half == 0)
        rout4[sl] = make_float4(acc.x * invz, acc.y * invz, acc.z * invz, acc.w * invz);

    int h2 = lane & 3, g = lane >> 2;
    float er2 = erf[d * 4 + h2];
    float f0 = eef[h2], f1 = eef[4 + h2], f2 = eef[8 + h2];
    float invz2 = __shfl_sync(0xffffffffu, invz, h2 * 4);
    for (int e0 = start; e0 < end; e0 += 8) {
        int ei = e0 + g;
        if (ei < end) {
            int2 me = g_es[ei];
            int t = me.y & 3;
            float eet = (t == 0) ? f0 : ((t == 1) ? f1 : f2);
            float sc = elf[me.x * 4 + h2] + er2 + eet;
            sc = sc > 0.f ? sc : NEG_SLOPE * sc;
            __stcs(&out_a[(long)(me.y >> 2) * 4 + h2], __expf(sc) * invz2);
        }
    }
}

// ---------------- launch ------------------------------------------------------
extern "C" void kernel_launch(void* const* d_in, const int* in_sizes, int n_in,
                              void* d_out, int out_size) {
    const float* x        = (const float*)d_in[0];
    const float* W        = (const float*)d_in[1];
    const float* W_e      = (const float*)d_in[2];
    const float* attn_l   = (const float*)d_in[3];
    const float* attn_r   = (const float*)d_in[4];
    const float* attn_e   = (const float*)d_in[5];
    const float* edge_emb = (const float*)d_in[6];
    const int*   src      = (const int*)d_in[7];
    const int*   dst      = (const int*)d_in[8];
    const int*   et       = (const int*)d_in[9];

    float* rst   = (float*)d_out;
    float* out_a = rst + (long)N_NODES * HD;

    int nb = (N_NODES + 255) / 256;
    int eb = (N_EDGES + 255) / 256;

    k_init<<<nb, 256>>>();
    k_ee<<<1, 384>>>(W_e, attn_e, edge_emb);
    k_hist<<<eb, 256>>>(dst);
    k_gemm<<<(N_NODES + 127) / 128, 256>>>(x, W, attn_l, attn_r);   // 4th: profiled
    k_scan1<<<NB, SCAN_B>>>();
    k_scan2<<<1, 128>>>();
    k_scan3<<<nb, 256>>>();
    k_scatter<<<eb, 256>>>(src, dst, et);
    k_agg<<<(N_NODES * 32 + 255) / 256, 256>>>(rst, out_a);
}

// round 9
// speedup vs baseline: 1.2614x; 1.0303x over previous
#include <cuda_runtime.h>
#include <cstdint>

#define N_NODES   100000
#define N_EDGES   1600000
#define N_ETYPES  3
#define IN_FEATS  128
#define HEADS     4
#define OUT_FEATS 16
#define HD        64
#define NEG_SLOPE 0.2f
#define SCAN_B    1024
#define NB        ((N_NODES + SCAN_B - 1) / SCAN_B)   // 98

// ---------------- device scratch (static globals; no allocation) -------------
__device__ float4 g_feat[N_NODES * 16];   // [N][64] as 16 x float4 (25.6 MB)
__device__ float4 g_el[N_NODES];          // [N][4]
__device__ float4 g_er[N_NODES];          // [N][4]
__device__ float4 g_ee[N_ETYPES];         // [3][4]
__device__ int    g_cnt[N_NODES];
__device__ int    g_incl[N_NODES];
__device__ int    g_bsum[NB];
__device__ int    g_boff[NB];
__device__ int    g_rowptr[N_NODES + 1];
__device__ int    g_cur[N_NODES];
__device__ int2   g_es[N_EDGES];          // sorted: {src, orig_id*4 | etype}

__device__ __forceinline__ uint32_t to_tf32(float f) {
    uint32_t r;
    asm("cvt.rna.tf32.f32 %0, %1;" : "=r"(r) : "f"(f));
    return r;
}

__device__ __forceinline__ void mma_tf32(float* c, const uint32_t* a, const uint32_t* b) {
    asm("mma.sync.aligned.m16n8k8.row.col.f32.tf32.tf32.f32 "
        "{%0,%1,%2,%3}, {%4,%5,%6,%7}, {%8,%9}, {%0,%1,%2,%3};"
        : "+f"(c[0]), "+f"(c[1]), "+f"(c[2]), "+f"(c[3])
        : "r"(a[0]), "r"(a[1]), "r"(a[2]), "r"(a[3]), "r"(b[0]), "r"(b[1]));
}

__device__ __forceinline__ void cp_async16(void* dst, const void* src, bool valid) {
    uint32_t d = (uint32_t)__cvta_generic_to_shared(dst);
    int sz = valid ? 16 : 0;
    asm volatile("cp.async.cg.shared.global [%0], [%1], 16, %2;"
                 :: "r"(d), "l"(src), "r"(sz));
}

// ---------------- init: zero histogram ---------------------------------------
__global__ void k_init() {
    int i = blockIdx.x * 256 + threadIdx.x;
    if (i < N_NODES) g_cnt[i] = 0;
}

// ---------------- per-etype edge term ee[t][h] -------------------------------
__global__ void k_ee(const float* __restrict__ W_e, const float* __restrict__ attn_e,
                     const float* __restrict__ edge_emb) {
    int w = threadIdx.x >> 5, lane = threadIdx.x & 31;
    if (w >= N_ETYPES * HEADS) return;
    int t = w >> 2, h = w & 3;
    float acc = 0.0f;
#pragma unroll
    for (int ei = 0; ei < 2; ei++) {
        int e = lane + ei * 32;
        float dot = 0.0f;
#pragma unroll 8
        for (int k = 0; k < 64; k++)
            dot += edge_emb[t * 64 + k] * W_e[k * 256 + h * 64 + e];
        acc += dot * attn_e[h * 64 + e];
    }
#pragma unroll
    for (int o = 16; o; o >>= 1) acc += __shfl_xor_sync(0xffffffffu, acc, o);
    if (lane == 0) ((float*)g_ee)[t * 4 + h] = acc;
}

// ---------------- counting sort: histogram ------------------------------------
__global__ __launch_bounds__(256) void k_hist(const int* __restrict__ dst) {
    int i = blockIdx.x * 256 + threadIdx.x;
    if (i < N_EDGES) atomicAdd(&g_cnt[dst[i]], 1);
}

// ---------------- GEMM: feat = x @ W via tf32 HMMA, cp.async 2-stage ---------
// 128x64 per block, 8 warps (4x2), warp tile 32x32 = 2(m16) x 4(n8) frags.
// Raw fp32 staged via cp.async; tf32 conversion at fragment-load time.
#define AS_STRIDE 40
#define BS_STRIDE 72
#define AS_WORDS  (128 * AS_STRIDE)      // 5120
#define BS_WORDS  (32 * BS_STRIDE)       // 2304
#define GEMM_SMEM ((2 * (AS_WORDS + BS_WORDS)) * 4)   // 59392 B

__global__ __launch_bounds__(256) void k_gemm(const float* __restrict__ x,
                                              const float* __restrict__ W,
                                              const float* __restrict__ attn_l,
                                              const float* __restrict__ attn_r) {
    extern __shared__ float smem[];
    float* AsF = smem;                       // [2][128][40]
    float* BsF = smem + 2 * AS_WORDS;        // [2][32][72]

    int tid  = threadIdx.x;
    int lane = tid & 31, wid = tid >> 5;
    int warp_m = wid & 3, warp_n = wid >> 2;
    int g = lane >> 2, t = lane & 3;
    int rbase = warp_m * 32, cbase = warp_n * 32;
    int rb = blockIdx.x * 128;

    float acc[2][4][4] = {};

    // stage issue for k-tile kt into buffer b
    auto stage = [&](int kt, int b) {
#pragma unroll
        for (int i = 0; i < 4; i++) {
            int s4 = tid + 256 * i;          // A float4 slot 0..1023
            int row = s4 >> 3, kq = s4 & 7;
            int gr = rb + row;
            int kp = kq ^ ((row >> 2) & 1);
            cp_async16(&AsF[b * AS_WORDS + row * AS_STRIDE + kp * 4],
                       &x[(long)gr * IN_FEATS + kt * 32 + kq * 4], gr < N_NODES);
        }
#pragma unroll
        for (int i = 0; i < 2; i++) {
            int s4 = tid + 256 * i;          // B float4 slot 0..511
            int k = s4 >> 4, c4 = s4 & 15;
            cp_async16(&BsF[b * BS_WORDS + k * BS_STRIDE + c4 * 4],
                       &W[(long)(kt * 32 + k) * HD + c4 * 4], true);
        }
        asm volatile("cp.async.commit_group;");
    };

    stage(0, 0);
    int s = 0;

#pragma unroll
    for (int kt = 0; kt < 4; kt++) {
        if (kt < 3) stage(kt + 1, s ^ 1);
        if (kt < 3) asm volatile("cp.async.wait_group 1;");
        else        asm volatile("cp.async.wait_group 0;");
        __syncthreads();

        const float* Ac = &AsF[s * AS_WORDS];
        const float* Bc = &BsF[s * BS_WORDS];
#pragma unroll
        for (int ks = 0; ks < 4; ks++) {
            int kk = ks * 8;
            uint32_t a[2][4];
#pragma unroll
            for (int mt = 0; mt < 2; mt++) {
                int r0 = rbase + mt * 16 + g;
                int c0 = kk + t, c1 = kk + t + 4;
                int p0 = ((c0 >> 2) ^ ((r0 >> 2) & 1)) * 4 + (c0 & 3);
                int p0b = ((c0 >> 2) ^ (((r0 + 8) >> 2) & 1)) * 4 + (c0 & 3);
                int p1 = ((c1 >> 2) ^ ((r0 >> 2) & 1)) * 4 + (c1 & 3);
                int p1b = ((c1 >> 2) ^ (((r0 + 8) >> 2) & 1)) * 4 + (c1 & 3);
                a[mt][0] = to_tf32(Ac[r0 * AS_STRIDE + p0]);
                a[mt][1] = to_tf32(Ac[(r0 + 8) * AS_STRIDE + p0b]);
                a[mt][2] = to_tf32(Ac[r0 * AS_STRIDE + p1]);
                a[mt][3] = to_tf32(Ac[(r0 + 8) * AS_STRIDE + p1b]);
            }
            uint32_t b[4][2];
#pragma unroll
            for (int nt = 0; nt < 4; nt++) {
                int n = cbase + nt * 8 + g;
                b[nt][0] = to_tf32(Bc[(kk + t) * BS_STRIDE + n]);
                b[nt][1] = to_tf32(Bc[(kk + t + 4) * BS_STRIDE + n]);
            }
#pragma unroll
            for (int mt = 0; mt < 2; mt++)
#pragma unroll
                for (int nt = 0; nt < 4; nt++)
                    mma_tf32(acc[mt][nt], a[mt], b[nt]);
        }
        __syncthreads();
        s ^= 1;
    }

    // ---- epilogue: feat store + el/er dots
    int hA = warp_n * 2, hB = hA + 1;
    float2 alA[2], arA[2], alB[2], arB[2];
#pragma unroll
    for (int q = 0; q < 2; q++) {
        alA[q] = *(const float2*)&attn_l[hA * 16 + q * 8 + t * 2];
        arA[q] = *(const float2*)&attn_r[hA * 16 + q * 8 + t * 2];
        alB[q] = *(const float2*)&attn_l[hB * 16 + q * 8 + t * 2];
        arB[q] = *(const float2*)&attn_r[hB * 16 + q * 8 + t * 2];
    }
    float* gfeat = (float*)g_feat;
#pragma unroll
    for (int mt = 0; mt < 2; mt++)
#pragma unroll
    for (int rr = 0; rr < 2; rr++) {
        int r = rb + rbase + mt * 16 + g + rr * 8;
        float v[4][2];
#pragma unroll
        for (int nt = 0; nt < 4; nt++) {
            v[nt][0] = acc[mt][nt][rr * 2];
            v[nt][1] = acc[mt][nt][rr * 2 + 1];
        }
        if (r < N_NODES) {
#pragma unroll
            for (int nt = 0; nt < 4; nt++)
                *(float2*)&gfeat[(long)r * HD + cbase + nt * 8 + t * 2] =
                    make_float2(v[nt][0], v[nt][1]);
        }
        float elA = v[0][0] * alA[0].x + v[0][1] * alA[0].y + v[1][0] * alA[1].x + v[1][1] * alA[1].y;
        float erA = v[0][0] * arA[0].x + v[0][1] * arA[0].y + v[1][0] * arA[1].x + v[1][1] * arA[1].y;
        float elB = v[2][0] * alB[0].x + v[2][1] * alB[0].y + v[3][0] * alB[1].x + v[3][1] * alB[1].y;
        float erB = v[2][0] * arB[0].x + v[2][1] * arB[0].y + v[3][0] * arB[1].x + v[3][1] * arB[1].y;
#pragma unroll
        for (int o = 1; o <= 2; o <<= 1) {
            elA += __shfl_xor_sync(0xffffffffu, elA, o);
            erA += __shfl_xor_sync(0xffffffffu, erA, o);
            elB += __shfl_xor_sync(0xffffffffu, elB, o);
            erB += __shfl_xor_sync(0xffffffffu, erB, o);
        }
        if (t == 0 && r < N_NODES) {
            ((float*)g_el)[r * 4 + hA] = elA;
            ((float*)g_el)[r * 4 + hB] = elB;
            ((float*)g_er)[r * 4 + hA] = erA;
            ((float*)g_er)[r * 4 + hB] = erB;
        }
    }
}

// ---------------- counting sort: scan + scatter -------------------------------
__global__ __launch_bounds__(SCAN_B) void k_scan1() {
    __shared__ int sh[SCAN_B];
    int b = blockIdx.x, t = threadIdx.x;
    int i = b * SCAN_B + t;
    sh[t] = (i < N_NODES) ? g_cnt[i] : 0;
#pragma unroll
    for (int o = 1; o < SCAN_B; o <<= 1) {
        __syncthreads();
        int add = (t >= o) ? sh[t - o] : 0;
        __syncthreads();
        sh[t] += add;
    }
    __syncthreads();
    if (i < N_NODES) g_incl[i] = sh[t];
    if (t == SCAN_B - 1) g_bsum[b] = sh[t];
}

__global__ void k_scan2() {
    __shared__ int sh[128];
    int t = threadIdx.x;
    int v = (t < NB) ? g_bsum[t] : 0;
    sh[t] = v;
#pragma unroll
    for (int o = 1; o < 128; o <<= 1) {
        __syncthreads();
        int add = (t >= o) ? sh[t - o] : 0;
        __syncthreads();
        sh[t] += add;
    }
    __syncthreads();
    if (t < NB) g_boff[t] = sh[t] - v;   // exclusive
}

__global__ void k_scan3() {
    int i = blockIdx.x * 256 + threadIdx.x;
    if (i < N_NODES) {
        int s = g_boff[i >> 10] + g_incl[i] - g_cnt[i];
        g_rowptr[i] = s;
        g_cur[i] = s;
    }
    if (i == 0) g_rowptr[N_NODES] = N_EDGES;
}

__global__ __launch_bounds__(256) void k_scatter(const int* __restrict__ src,
                                                 const int* __restrict__ dst,
                                                 const int* __restrict__ et) {
    int i = blockIdx.x * 256 + threadIdx.x;
    if (i >= N_EDGES) return;
    int p = atomicAdd(&g_cur[dst[i]], 1);
    g_es[p] = make_int2(src[i], (i << 2) | et[i]);
}

// ---------------- fused softmax + aggregate: one warp per dst node -----------
__global__ __launch_bounds__(256) void k_agg(float* __restrict__ rst,
                                             float* __restrict__ out_a) {
    int d = (blockIdx.x * 256 + threadIdx.x) >> 5;
    int lane = threadIdx.x & 31;
    if (d >= N_NODES) return;
    int start = g_rowptr[d], end = g_rowptr[d + 1];
    float4* rout4 = (float4*)(rst + (long)d * HD);
    int sl = lane & 15, half = lane >> 4;
    if (start == end) {
        if (half == 0) rout4[sl] = make_float4(0.f, 0.f, 0.f, 0.f);
        return;
    }

    const float* elf = (const float*)g_el;
    const float* erf = (const float*)g_er;
    const float* eef = (const float*)g_ee;

    int h = sl >> 2;
    float erh = erf[d * 4 + h];
    float ee0 = eef[h], ee1 = eef[4 + h], ee2 = eef[8 + h];

    float z = 0.f;
    float4 acc = make_float4(0.f, 0.f, 0.f, 0.f);
    int e = start + half;
    int2 m = (e < end) ? g_es[e] : make_int2(0, 0);
    for (; e < end; e += 2) {
        int2 mn = m;
        if (e + 2 < end) mn = g_es[e + 2];
        int t = m.y & 3;
        float eet = (t == 0) ? ee0 : ((t == 1) ? ee1 : ee2);
        float sc = elf[m.x * 4 + h] + erh + eet;
        sc = sc > 0.f ? sc : NEG_SLOPE * sc;
        float ev = __expf(sc);
        float4 f = g_feat[(long)m.x * 16 + sl];
        z += ev;
        acc.x += f.x * ev; acc.y += f.y * ev;
        acc.z += f.z * ev; acc.w += f.w * ev;
        m = mn;
    }
    z     += __shfl_xor_sync(0xffffffffu, z, 16);
    acc.x += __shfl_xor_sync(0xffffffffu, acc.x, 16);
    acc.y += __shfl_xor_sync(0xffffffffu, acc.y, 16);
    acc.z += __shfl_xor_sync(0xffffffffu, acc.z, 16);
    acc.w += __shfl_xor_sync(0xffffffffu, acc.w, 16);
    float invz = 1.0f / z;
    if (half == 0)
        rout4[sl] = make_float4(acc.x * invz, acc.y * invz, acc.z * invz, acc.w * invz);

    int h2 = lane & 3, g = lane >> 2;
    float er2 = erf[d * 4 + h2];
    float f0 = eef[h2], f1 = eef[4 + h2], f2 = eef[8 + h2];
    float invz2 = __shfl_sync(0xffffffffu, invz, h2 * 4);
    for (int e0 = start; e0 < end; e0 += 8) {
        int ei = e0 + g;
        if (ei < end) {
            int2 me = g_es[ei];
            int t = me.y & 3;
            float eet = (t == 0) ? f0 : ((t == 1) ? f1 : f2);
            float sc = elf[me.x * 4 + h2] + er2 + eet;
            sc = sc > 0.f ? sc : NEG_SLOPE * sc;
            __stcs(&out_a[(long)(me.y >> 2) * 4 + h2], __expf(sc) * invz2);
        }
    }
}

// ---------------- launch ------------------------------------------------------
extern "C" void kernel_launch(void* const* d_in, const int* in_sizes, int n_in,
                              void* d_out, int out_size) {
    const float* x        = (const float*)d_in[0];
    const float* W        = (const float*)d_in[1];
    const float* W_e      = (const float*)d_in[2];
    const float* attn_l   = (const float*)d_in[3];
    const float* attn_r   = (const float*)d_in[4];
    const float* attn_e   = (const float*)d_in[5];
    const float* edge_emb = (const float*)d_in[6];
    const int*   src      = (const int*)d_in[7];
    const int*   dst      = (const int*)d_in[8];
    const int*   et       = (const int*)d_in[9];

    float* rst   = (float*)d_out;
    float* out_a = rst + (long)N_NODES * HD;

    int nb = (N_NODES + 255) / 256;
    int eb = (N_EDGES + 255) / 256;

    cudaFuncSetAttribute(k_gemm, cudaFuncAttributeMaxDynamicSharedMemorySize, GEMM_SMEM);

    k_init<<<nb, 256>>>();
    k_ee<<<1, 384>>>(W_e, attn_e, edge_emb);
    k_hist<<<eb, 256>>>(dst);
    k_gemm<<<(N_NODES + 127) / 128, 256, GEMM_SMEM>>>(x, W, attn_l, attn_r);   // 4th: profiled
    k_scan1<<<NB, SCAN_B>>>();
    k_scan2<<<1, 128>>>();
    k_scan3<<<nb, 256>>>();
    k_scatter<<<eb, 256>>>(src, dst, et);
    k_agg<<<(N_NODES * 32 + 255) / 256, 256>>>(rst, out_a);
}